// round 15
// baseline (speedup 1.0000x reference)
#include <cuda_runtime.h>
#include <cuda_bf16.h>

// Problem: B=64, T=4096, D=256
//   mids[b,d]  = sum_e W[d,e] * q[b,e]
//   s[b,t]     = tanh( sum_d k[b,t,d]*mids[b,d] + bias )
//   e[b,t]     = exp(s[b,t]) * m[b,t]     (max-subtraction cancels: tanh bounded)
//   attn[b,t]  = e[b,t] / sum_t e[b,t]
//
// Inputs: q[B,D], k[B,T,D], m[B,T], W[D,D], bias[1]   Output: attn[B,T] f32

#define BATCH 64
#define TT    4096
#define DD    256

__device__ float g_mids[BATCH * DD];

// ---------------- Kernel A: mids = W @ q (R3 best: 512 blocks) ---------------
// grid = (D/32, B), block = 256 (8 warps), warp computes 4 outputs.
// Each lane: 10 independent LDG.128 (2 q + 8 W) in flight, shuffle reduce.
__global__ void kA_mids(const float* __restrict__ q,
                        const float* __restrict__ W) {
    const int tid  = threadIdx.x;
    const int warp = tid >> 5;
    const int lane = tid & 31;

    cudaTriggerProgrammaticLaunchCompletion();

    const int b      = blockIdx.y;
    const int d_base = blockIdx.x * 32 + warp * 4;
    const float4* qv = reinterpret_cast<const float4*>(q + b * DD);
    const float4 x0 = __ldg(qv + lane);
    const float4 x1 = __ldg(qv + lane + 32);

    float acc[4];
#pragma unroll
    for (int i = 0; i < 4; ++i) {
        const float4* Wrow = reinterpret_cast<const float4*>(W + (d_base + i) * DD);
        float4 w0 = __ldg(Wrow + lane);
        float4 w1 = __ldg(Wrow + lane + 32);
        acc[i] = w0.x * x0.x + w0.y * x0.y + w0.z * x0.z + w0.w * x0.w
               + w1.x * x1.x + w1.y * x1.y + w1.z * x1.z + w1.w * x1.w;
    }

#pragma unroll
    for (int off = 16; off > 0; off >>= 1) {
#pragma unroll
        for (int i = 0; i < 4; ++i)
            acc[i] += __shfl_down_sync(0xffffffffu, acc[i], off);
    }

    if (lane == 0) {
        reinterpret_cast<float4*>(g_mids + b * DD + d_base)[0] =
            make_float4(acc[0], acc[1], acc[2], acc[3]);
    }
}

// ---------------- Kernel B: e[b,t] = exp(tanh(k.mids + bias)) * m -------------
// (R3 configuration — best measured.) grid = (T/16, B), block = 256 (8 warps),
// two t's per warp (4 LDG.128/lane front-batched). PDL secondary: k/m loads
// issue BEFORE the grid-dependency sync so they overlap kA. Results staged in
// smem -> one coalesced 64B store per block.
__global__ void kB_scores(const float* __restrict__ k,
                          const float* __restrict__ m,
                          const float* __restrict__ bias,
                          float* __restrict__ e_out) {
    __shared__ float smids[DD];
    __shared__ float se[16];
    const int b    = blockIdx.y;
    const int tid  = threadIdx.x;
    const int warp = tid >> 5;
    const int lane = tid & 31;

    const int t0 = blockIdx.x * 16 + warp * 2;

    const float4* krow0 = reinterpret_cast<const float4*>(
        k + ((size_t)b * TT + t0) * DD);
    const float4* krow1 = krow0 + (DD / 4);

    // Independent of kA: issue these loads first.
    float4 a0 = krow0[lane];
    float4 a1 = krow0[lane + 32];
    float4 c0 = krow1[lane];
    float4 c1 = krow1[lane + 32];
    float mw0 = 0.f, mw1 = 0.f;
    if (lane == 0) {
        mw0 = m[(size_t)b * TT + t0];
        mw1 = m[(size_t)b * TT + t0 + 1];
    }

    cudaGridDependencySynchronize();

    smids[tid] = g_mids[b * DD + tid];
    __syncthreads();

    const float4* mv = reinterpret_cast<const float4*>(smids);
    float4 m0 = mv[lane];
    float4 m1 = mv[lane + 32];

    float acc0 = a0.x * m0.x + a0.y * m0.y + a0.z * m0.z + a0.w * m0.w
               + a1.x * m1.x + a1.y * m1.y + a1.z * m1.z + a1.w * m1.w;
    float acc1 = c0.x * m0.x + c0.y * m0.y + c0.z * m0.z + c0.w * m0.w
               + c1.x * m1.x + c1.y * m1.y + c1.z * m1.z + c1.w * m1.w;

#pragma unroll
    for (int off = 16; off > 0; off >>= 1) {
        acc0 += __shfl_down_sync(0xffffffffu, acc0, off);
        acc1 += __shfl_down_sync(0xffffffffu, acc1, off);
    }

    if (lane == 0) {
        const float bb = bias[0];
        se[warp * 2]     = __expf(tanhf(acc0 + bb)) * mw0;
        se[warp * 2 + 1] = __expf(tanhf(acc1 + bb)) * mw1;
    }
    __syncthreads();

    if (tid < 16)
        e_out[(size_t)b * TT + blockIdx.x * 16 + tid] = se[tid];
}

// ---------------- Kernel C: normalize, redundant-sum (no block dependency) ----
// grid = (16, B) = 1024 blocks, block = 256. Each block reads its batch's FULL
// e row (16KB, L2-resident after kB), block-reduces the sum redundantly, and
// normalizes only its 1/16 slice. 16x the parallelism of one-block-per-batch,
// zero cross-block communication, deterministic.
__global__ void kC_norm(float* __restrict__ e_io) {
    __shared__ float warp_sums[8];
    __shared__ float s_inv;
    const int b     = blockIdx.y;
    const int slice = blockIdx.x;          // this block normalizes float4 idx [64*slice, 64*slice+64)
    const int tid   = threadIdx.x;

    cudaGridDependencySynchronize();

    float4* row = reinterpret_cast<float4*>(e_io + (size_t)b * TT);

    float4 v[4];
#pragma unroll
    for (int i = 0; i < 4; ++i) v[i] = row[tid + i * 256];

    float acc = 0.f;
#pragma unroll
    for (int i = 0; i < 4; ++i)
        acc += v[i].x + v[i].y + v[i].z + v[i].w;

#pragma unroll
    for (int off = 16; off > 0; off >>= 1)
        acc += __shfl_down_sync(0xffffffffu, acc, off);
    if ((tid & 31) == 0) warp_sums[tid >> 5] = acc;
    __syncthreads();

    if (tid == 0) {
        float s = warp_sums[0] + warp_sums[1] + warp_sums[2] + warp_sums[3]
                + warp_sums[4] + warp_sums[5] + warp_sums[6] + warp_sums[7];
        s_inv = 1.f / s;
    }
    __syncthreads();
    const float inv = s_inv;

    // Write back only this block's slice (values already in registers).
#pragma unroll
    for (int i = 0; i < 4; ++i) {
        const int idx = tid + i * 256;
        if ((idx >> 6) == slice) {
            float4 r = v[i];
            r.x *= inv; r.y *= inv; r.z *= inv; r.w *= inv;
            row[idx] = r;
        }
    }
}

extern "C" void kernel_launch(void* const* d_in, const int* in_sizes, int n_in,
                              void* d_out, int out_size) {
    const float* q    = (const float*)d_in[0];
    const float* k    = (const float*)d_in[1];
    const float* m    = (const float*)d_in[2];
    const float* W    = (const float*)d_in[3];
    const float* bias = (const float*)d_in[4];
    float* out = (float*)d_out;

    // kA: plain launch
    {
        dim3 g(DD / 32, BATCH);
        kA_mids<<<g, 256>>>(q, W);
    }

    // kB: PDL secondary of kA
    {
        cudaLaunchAttribute at[1];
        at[0].id = cudaLaunchAttributeProgrammaticStreamSerialization;
        at[0].val.programmaticStreamSerializationAllowed = 1;
        cudaLaunchConfig_t cfg = {};
        cfg.gridDim  = dim3(TT / 16, BATCH);
        cfg.blockDim = dim3(256);
        cfg.stream   = 0;
        cfg.attrs    = at;
        cfg.numAttrs = 1;
        cudaLaunchKernelEx(&cfg, kB_scores, k, m, bias, out);
    }

    // kC: PDL secondary of kB (launch-latency hiding)
    {
        cudaLaunchAttribute at[1];
        at[0].id = cudaLaunchAttributeProgrammaticStreamSerialization;
        at[0].val.programmaticStreamSerializationAllowed = 1;
        cudaLaunchConfig_t cfg = {};
        cfg.gridDim  = dim3(16, BATCH);
        cfg.blockDim = dim3(256);
        cfg.stream   = 0;
        cfg.attrs    = at;
        cfg.numAttrs = 1;
        cudaLaunchKernelEx(&cfg, kC_norm, out);
    }
}